// round 5
// baseline (speedup 1.0000x reference)
#include <cuda_runtime.h>

// Fused YOLO decode, single launch.
// Scales 52 & 26: one thread per 4 consecutive cells, channel reads as
// float4 (LDG.128), per-anchor register reuse + incremental argmax to keep
// regs <= 85 (6 CTAs/SM -> near-single-wave on 148 SMs). Scale 13 (HW=169,
// odd): scalar path. Boxes staged via smem -> dense STG.128.
// Output: boxes [N,6] in scale order 13,26,52, then mask [N].

#define TPB 128

#define VBLK52 676   // 128*52*52 cells / 4 / 128
#define VBLK26 169   // 128*26*26 cells / 4 / 128
#define SBLK13 169   // 128*13*13 cells / 128

#define ROWS13 64896
#define ROWS26 259584
#define ROWS52 1038336
#define ROWBASE13 0
#define ROWBASE26 ROWS13
#define ROWBASE52 (ROWS13 + ROWS26)

__device__ __forceinline__ float f4c(const float4& q, int i) {
    switch (i) {
        case 0: return q.x;
        case 1: return q.y;
        case 2: return q.z;
        default: return q.w;
    }
}

template<int W, int HW, int STRIDE>
__device__ __forceinline__ void vec_path(const float* __restrict__ in,
                                         const float* __restrict__ anchors,
                                         float thr,
                                         float* __restrict__ boxes,
                                         float* __restrict__ mask,
                                         size_t rowbase,
                                         int blk, int t, float* s)
{
    const int cell0 = (blk * TPB + t) * 4;      // HW%4==0: no batch crossing
    const int b   = cell0 / HW;                 // compile-time HW -> mul/shift
    const int cw0 = cell0 - b * HW;
    constexpr int HW4 = HW / 4;

    const float4* base = (const float4*)(in + (size_t)b * 45 * HW + cw0);

    float fw[4], fh[4];
    #pragma unroll
    for (int i = 0; i < 4; ++i) {
        const int cw = cw0 + i;
        const int h = cw / W;                   // compile-time W
        fw[i] = (float)(cw - h * W);
        fh[i] = (float)h;
    }

    unsigned mbits = 0;

    #pragma unroll
    for (int a = 0; a < 3; ++a) {
        const float4* p = base + (size_t)(a * 15) * HW4;

        const float4 v0 = __ldg(p + 0 * (size_t)HW4);
        const float4 v1 = __ldg(p + 1 * (size_t)HW4);
        const float4 v2 = __ldg(p + 2 * (size_t)HW4);
        const float4 v3 = __ldg(p + 3 * (size_t)HW4);
        const float4 v4 = __ldg(p + 4 * (size_t)HW4);

        // incremental argmax: only one class vector live at a time
        float4 c0 = __ldg(p + 5 * (size_t)HW4);
        float best[4] = { c0.x, c0.y, c0.z, c0.w };
        int   bi[4]   = { 0, 0, 0, 0 };
        #pragma unroll
        for (int c = 1; c < 10; ++c) {
            const float4 q = __ldg(p + (size_t)(5 + c) * HW4);
            #pragma unroll
            for (int i = 0; i < 4; ++i) {
                const float qv = f4c(q, i);
                if (qv > best[i]) { best[i] = qv; bi[i] = c; }
            }
        }

        const float aw = __ldg(anchors + 2 * a + 0);
        const float ah = __ldg(anchors + 2 * a + 1);

        #pragma unroll
        for (int i = 0; i < 4; ++i) {
            const float o0 = f4c(v0, i);
            const float px = (fw[i] + f4c(v1, i)) * (float)STRIDE;
            const float py = (fh[i] + f4c(v2, i)) * (float)STRIDE;
            const float pw = aw * __expf(f4c(v3, i));
            const float ph = ah * __expf(f4c(v4, i));

            float* r = s + (t * 4 + i) * 18 + a * 6;
            r[0] = o0;
            r[1] = px - 0.5f * pw;
            r[2] = py - 0.5f * ph;
            r[3] = px + 0.5f * pw;
            r[4] = py + 0.5f * ph;
            r[5] = (float)bi[i];

            if (o0 > thr) mbits |= 1u << (i * 3 + a);
        }
    }

    // mask: 12 contiguous floats per thread -> 3 STG.128
    float4* mp = (float4*)(mask + rowbase + (size_t)blk * TPB * 12 + t * 12);
    #pragma unroll
    for (int k = 0; k < 3; ++k) {
        float4 mv;
        mv.x = (mbits >> (k * 4 + 0)) & 1u ? 1.0f : 0.0f;
        mv.y = (mbits >> (k * 4 + 1)) & 1u ? 1.0f : 0.0f;
        mv.z = (mbits >> (k * 4 + 2)) & 1u ? 1.0f : 0.0f;
        mv.w = (mbits >> (k * 4 + 3)) & 1u ? 1.0f : 0.0f;
        mp[k] = mv;
    }

    __syncthreads();

    // boxes: 9216 floats per CTA = 2304 float4, 18 per thread, coalesced
    float4* ob = (float4*)(boxes + rowbase * 6 + (size_t)blk * TPB * 72);
    const float4* sb = (const float4*)s;
    #pragma unroll
    for (int k = 0; k < 18; ++k)
        ob[k * TPB + t] = sb[k * TPB + t];
}

__global__ __launch_bounds__(TPB, 6)
void decode_fused_kernel(const float* __restrict__ in13,
                         const float* __restrict__ in26,
                         const float* __restrict__ in52,
                         const float* __restrict__ anc13,
                         const float* __restrict__ anc26,
                         const float* __restrict__ anc52,
                         const float* __restrict__ thresh_p,
                         float* __restrict__ boxes,
                         float* __restrict__ mask)
{
    __shared__ float s[4 * TPB * 18];   // 36,864 B

    const int bid = blockIdx.x;
    const int t = threadIdx.x;
    const float thr = __ldg(thresh_p);

    if (bid < VBLK52) {
        vec_path<52, 2704, 8>(in52, anc52, thr, boxes, mask,
                              (size_t)ROWBASE52, bid, t, s);
    } else if (bid < VBLK52 + VBLK26) {
        vec_path<26, 676, 16>(in26, anc26, thr, boxes, mask,
                              (size_t)ROWBASE26, bid - VBLK52, t, s);
    } else {
        // ---------------- scalar path: scale 13 ----------------
        const int blk = bid - (VBLK52 + VBLK26);
        const int HW = 169, W = 13;
        const float stride = 32.0f;

        const int cell = blk * TPB + t;
        const int b  = cell / HW;
        const int cw = cell - b * HW;
        const int h  = cw / W;
        const int w  = cw - h * W;

        const float fw = (float)w;
        const float fh = (float)h;
        const float* base = in13 + (size_t)b * 45 * HW + cw;

        float msk[3];

        #pragma unroll
        for (int a = 0; a < 3; ++a) {
            const float* p = base + (size_t)(a * 15) * HW;
            const float c0 = __ldg(p + 0 * (size_t)HW);
            const float c1 = __ldg(p + 1 * (size_t)HW);
            const float c2 = __ldg(p + 2 * (size_t)HW);
            const float c3 = __ldg(p + 3 * (size_t)HW);
            const float c4 = __ldg(p + 4 * (size_t)HW);

            float best = __ldg(p + 5 * (size_t)HW);
            int bi = 0;
            #pragma unroll
            for (int c = 1; c < 10; ++c) {
                const float q = __ldg(p + (size_t)(5 + c) * HW);
                if (q > best) { best = q; bi = c; }
            }

            const float px = (fw + c1) * stride;
            const float py = (fh + c2) * stride;
            const float pw = __ldg(anc13 + 2 * a + 0) * __expf(c3);
            const float ph = __ldg(anc13 + 2 * a + 1) * __expf(c4);

            float* r = s + t * 18 + a * 6;
            r[0] = c0;
            r[1] = px - 0.5f * pw;
            r[2] = py - 0.5f * ph;
            r[3] = px + 0.5f * pw;
            r[4] = py + 0.5f * ph;
            r[5] = (float)bi;
            msk[a] = (c0 > thr) ? 1.0f : 0.0f;
        }

        const size_t mrow = (size_t)ROWBASE13 + (size_t)cell * 3;
        mask[mrow + 0] = msk[0];
        mask[mrow + 1] = msk[1];
        mask[mrow + 2] = msk[2];

        __syncthreads();

        float2* ob = (float2*)(boxes + (size_t)ROWBASE13 * 6 + (size_t)blk * TPB * 18);
        const float2* sb = (const float2*)s;
        #pragma unroll
        for (int k = 0; k < 9; ++k)
            ob[k * TPB + t] = sb[k * TPB + t];
    }
}

extern "C" void kernel_launch(void* const* d_in, const int* in_sizes, int n_in,
                              void* d_out, int out_size)
{
    const float* out13 = (const float*)d_in[0];
    const float* out26 = (const float*)d_in[1];
    const float* out52 = (const float*)d_in[2];
    const float* anc13 = (const float*)d_in[3];
    const float* anc26 = (const float*)d_in[4];
    const float* anc52 = (const float*)d_in[5];
    const float* thr   = (const float*)d_in[6];

    float* out = (float*)d_out;
    const int rowsTot = ROWS13 + ROWS26 + ROWS52;   // 1,362,816

    float* boxes = out;                       // [rowsTot, 6]
    float* mask  = out + (size_t)rowsTot * 6; // [rowsTot]

    decode_fused_kernel<<<VBLK52 + VBLK26 + SBLK13, TPB>>>(
        out13, out26, out52, anc13, anc26, anc52, thr, boxes, mask);
}

// round 6
// speedup vs baseline: 1.1592x; 1.1592x over previous
#include <cuda_runtime.h>

// Fused YOLO decode, single launch, warp-per-anchor.
// Block = 96 threads = 3 warps. Warp a processes anchor a for a contiguous
// span of 128 cells (4 cells/thread, float4 channel loads). Each thread
// issues ONE batch of 15 LDG.128 (max MLP, single scoreboard wait).
// Boxes staged in smem (conflict-free column layout) -> dense coalesced STG.
// Output: boxes [N,6] in scale order 13,26,52, then mask [N].

#define TPB 96

#define VBLK52 2704  // 128*52*52 cells / 128 cells-per-block
#define VBLK26 676   // 128*26*26 / 128
#define SBLK13 676   // 128*13*13 / 32 cells-per-block (scalar path)

#define ROWS13 64896
#define ROWS26 259584
#define ROWS52 1038336
#define ROWBASE13 0
#define ROWBASE26 ROWS13
#define ROWBASE52 (ROWS13 + ROWS26)

__device__ __forceinline__ float f4c(const float4& q, int i) {
    switch (i) {
        case 0: return q.x;
        case 1: return q.y;
        case 2: return q.z;
        default: return q.w;
    }
}

// smem: vec path uses 2304 floats (column layout j*384 + (a*4+i)*32 + cg),
// scalar path uses 576 floats (j*96 + a*32 + cg).
template<int W, int HW, int STRIDE>
__device__ __forceinline__ void vec_path(const float* __restrict__ in,
                                         const float* __restrict__ anchors,
                                         float thr,
                                         float* __restrict__ boxes,
                                         float* __restrict__ mask,
                                         size_t rowbase,
                                         int blk, int a, int cg, int t,
                                         float* __restrict__ s)
{
    constexpr int HW4 = HW / 4;
    const int cell0 = (blk * 32 + cg) * 4;      // HW%4==0: no batch crossing
    const int b   = cell0 / HW;                 // compile-time HW
    const int cw0 = cell0 - b * HW;

    const float4* p = (const float4*)(in + (size_t)b * 45 * HW
                                         + (size_t)a * 15 * HW + cw0);

    // ONE batch of 15 wide loads -> single long-scoreboard wait
    float4 v[15];
    #pragma unroll
    for (int c = 0; c < 15; ++c)
        v[c] = __ldg(p + (size_t)c * HW4);

    const float aw = __ldg(anchors + 2 * a + 0);
    const float ah = __ldg(anchors + 2 * a + 1);

    #pragma unroll
    for (int i = 0; i < 4; ++i) {
        const int cw = cw0 + i;
        const int h = cw / W;                   // compile-time W
        const float fw = (float)(cw - h * W);
        const float fh = (float)h;

        const float o0 = f4c(v[0], i);

        float best = f4c(v[5], i);
        int bi = 0;
        #pragma unroll
        for (int c = 1; c < 10; ++c) {
            const float q = f4c(v[5 + c], i);
            if (q > best) { best = q; bi = c; }
        }

        const float px = (fw + f4c(v[1], i)) * (float)STRIDE;
        const float py = (fh + f4c(v[2], i)) * (float)STRIDE;
        const float pw = aw * __expf(f4c(v[3], i));
        const float ph = ah * __expf(f4c(v[4], i));

        // conflict-free STS: lane (cg) stride 1 within each (a,i,j)
        const int base = (a * 4 + i) * 32 + cg;
        s[0 * 384 + base] = o0;
        s[1 * 384 + base] = px - 0.5f * pw;
        s[2 * 384 + base] = py - 0.5f * ph;
        s[3 * 384 + base] = px + 0.5f * pw;
        s[4 * 384 + base] = py + 0.5f * ph;
        s[5 * 384 + base] = (float)bi;

        mask[rowbase + (size_t)(cell0 + i) * 3 + a] = (o0 > thr) ? 1.0f : 0.0f;
    }

    __syncthreads();

    // copy out: 2304 floats per block; thread t -> rows 4t..4t+3 (24 floats)
    float buf[24];
    #pragma unroll
    for (int k = 0; k < 4; ++k) {
        const int r = t * 4 + k;
        const int cell = r / 3;                 // local cell 0..127
        const int aa = r - 3 * cell;
        const int ii = cell & 3;
        const int cc = cell >> 2;
        const int base = (aa * 4 + ii) * 32 + cc;
        #pragma unroll
        for (int j = 0; j < 6; ++j)
            buf[k * 6 + j] = s[j * 384 + base];
    }
    float4* ob = (float4*)(boxes + rowbase * 6 + (size_t)blk * 2304 + t * 24);
    #pragma unroll
    for (int m = 0; m < 6; ++m)
        ob[m] = make_float4(buf[4 * m], buf[4 * m + 1],
                            buf[4 * m + 2], buf[4 * m + 3]);
}

__global__ __launch_bounds__(TPB)
void decode_fused_kernel(const float* __restrict__ in13,
                         const float* __restrict__ in26,
                         const float* __restrict__ in52,
                         const float* __restrict__ anc13,
                         const float* __restrict__ anc26,
                         const float* __restrict__ anc52,
                         const float* __restrict__ thresh_p,
                         float* __restrict__ boxes,
                         float* __restrict__ mask)
{
    __shared__ float s[2304];   // 9216 B

    const int bid = blockIdx.x;
    const int t = threadIdx.x;
    const int a  = t >> 5;      // warp = anchor
    const int cg = t & 31;      // lane = cell-group
    const float thr = __ldg(thresh_p);

    if (bid < VBLK52) {
        vec_path<52, 2704, 8>(in52, anc52, thr, boxes, mask,
                              (size_t)ROWBASE52, bid, a, cg, t, s);
    } else if (bid < VBLK52 + VBLK26) {
        vec_path<26, 676, 16>(in26, anc26, thr, boxes, mask,
                              (size_t)ROWBASE26, bid - VBLK52, a, cg, t, s);
    } else {
        // ---- scalar path: scale 13, 32 cells/block, warp-per-anchor ----
        const int blk = bid - (VBLK52 + VBLK26);
        constexpr int HW = 169, W = 13;
        const float stride = 32.0f;

        const int cell = blk * 32 + cg;
        const int b  = cell / HW;
        const int cw = cell - b * HW;
        const int h  = cw / W;
        const int w  = cw - h * W;

        const float* p = in13 + (size_t)b * 45 * HW + (size_t)a * 15 * HW + cw;

        float v[15];
        #pragma unroll
        for (int c = 0; c < 15; ++c)
            v[c] = __ldg(p + (size_t)c * HW);

        float best = v[5];
        int bi = 0;
        #pragma unroll
        for (int c = 1; c < 10; ++c)
            if (v[5 + c] > best) { best = v[5 + c]; bi = c; }

        const float px = ((float)w + v[1]) * stride;
        const float py = ((float)h + v[2]) * stride;
        const float pw = __ldg(anc13 + 2 * a + 0) * __expf(v[3]);
        const float ph = __ldg(anc13 + 2 * a + 1) * __expf(v[4]);

        const int base = a * 32 + cg;           // conflict-free STS
        s[0 * 96 + base] = v[0];
        s[1 * 96 + base] = px - 0.5f * pw;
        s[2 * 96 + base] = py - 0.5f * ph;
        s[3 * 96 + base] = px + 0.5f * pw;
        s[4 * 96 + base] = py + 0.5f * ph;
        s[5 * 96 + base] = (float)bi;

        mask[(size_t)ROWBASE13 + (size_t)cell * 3 + a] = (v[0] > thr) ? 1.0f : 0.0f;

        __syncthreads();

        // 576 floats/block; thread t -> row t (6 floats)
        const int cc = t / 3;
        const int aa = t - 3 * cc;
        const int rb = aa * 32 + cc;
        float buf[6];
        #pragma unroll
        for (int j = 0; j < 6; ++j)
            buf[j] = s[j * 96 + rb];

        float2* ob = (float2*)(boxes + (size_t)ROWBASE13 * 6
                               + (size_t)blk * 576 + t * 6);
        ob[0] = make_float2(buf[0], buf[1]);
        ob[1] = make_float2(buf[2], buf[3]);
        ob[2] = make_float2(buf[4], buf[5]);
    }
}

extern "C" void kernel_launch(void* const* d_in, const int* in_sizes, int n_in,
                              void* d_out, int out_size)
{
    const float* out13 = (const float*)d_in[0];
    const float* out26 = (const float*)d_in[1];
    const float* out52 = (const float*)d_in[2];
    const float* anc13 = (const float*)d_in[3];
    const float* anc26 = (const float*)d_in[4];
    const float* anc52 = (const float*)d_in[5];
    const float* thr   = (const float*)d_in[6];

    float* out = (float*)d_out;
    const int rowsTot = ROWS13 + ROWS26 + ROWS52;   // 1,362,816

    float* boxes = out;                       // [rowsTot, 6]
    float* mask  = out + (size_t)rowsTot * 6; // [rowsTot]

    decode_fused_kernel<<<VBLK52 + VBLK26 + SBLK13, TPB>>>(
        out13, out26, out52, anc13, anc26, anc52, thr, boxes, mask);
}